// round 1
// baseline (speedup 1.0000x reference)
#include <cuda_runtime.h>

typedef unsigned long long u64;

// ---- packed f32x2 helpers (sm_100+; ptxas never emits FFMA2 from C++) ----
__device__ __forceinline__ u64 pack2(float a, float b){
    u64 r; asm("mov.b64 %0, {%1, %2};" : "=l"(r) : "f"(a), "f"(b)); return r;
}
__device__ __forceinline__ void fma2(u64 &d, u64 a, u64 b){
    asm("fma.rn.f32x2 %0, %1, %2, %0;" : "+l"(d) : "l"(a), "l"(b));
}
__device__ __forceinline__ float2 unpack2(u64 v){
    float2 r; asm("mov.b64 {%0, %1}, %2;" : "=f"(r.x), "=f"(r.y) : "l"(v)); return r;
}

constexpr int IN_DIM = 225;   // 15*15
constexpr int NS     = 7;     // n_scales
constexpr int HID    = 4;
constexpr int NC     = NS * HID;  // 28 fused output channels, c = s*4+h
constexpr int NTHREADS = 256;

__global__ __launch_bounds__(NTHREADS) void fused_msmlp_kernel(
    const float* __restrict__ x,
    const float* __restrict__ W1,   // [7,225,4]
    const float* __restrict__ b1,   // [7,4]
    const float* __restrict__ W2,   // [7,4,4]
    const float* __restrict__ b2,   // [7,4]
    float* __restrict__ out,        // [B]
    int B)
{
    // W1 restaged as [i][28] channel-major so channel pairs (2p,2p+1) are a
    // contiguous b64 word -> direct LDS operand for fma.rn.f32x2.
    __shared__ ulonglong2 w1q[IN_DIM][7];   // 25200 B, broadcast reads
    __shared__ float sb1[NC];
    __shared__ float sw2s[NC];              // sum_k W2[s,h,k]
    __shared__ float sb2s[NS];              // sum_k b2[s,k]

    float* w1f = (float*)w1q;
    for (int t = threadIdx.x; t < IN_DIM * NC; t += NTHREADS){
        int i = t / NC, c = t - i * NC;
        int s = c >> 2, h = c & 3;
        w1f[i * NC + c] = W1[(s * IN_DIM + i) * HID + h];
    }
    if (threadIdx.x < NC){
        int c = threadIdx.x;
        sb1[c] = b1[c];                     // [7,4] flat == c
        float w2s = 0.f;
        #pragma unroll
        for (int k = 0; k < HID; k++) w2s += W2[c * HID + k];
        sw2s[c] = w2s;
    }
    if (threadIdx.x < NS){
        int s = threadIdx.x;
        float bs = 0.f;
        #pragma unroll
        for (int k = 0; k < HID; k++) bs += b2[s * HID + k];
        sb2s[s] = bs;
    }
    __syncthreads();

    int row = blockIdx.x * NTHREADS + threadIdx.x;
    if (row >= B) return;
    const float* xr = x + (long long)row * IN_DIM;

    // 14 packed accumulators = 28 channels of (x @ W1_all)
    u64 acc[7 * 2];
    #pragma unroll
    for (int p = 0; p < 14; p++) acc[p] = 0ull;

    // 225 = 28*8 + 1 : chunked k-loop, 8 prefetched x scalars per chunk
    #pragma unroll 1
    for (int i0 = 0; i0 < 224; i0 += 8){
        float xv[8];
        #pragma unroll
        for (int j = 0; j < 8; j++) xv[j] = xr[i0 + j];
        #pragma unroll
        for (int j = 0; j < 8; j++){
            u64 xd = pack2(xv[j], xv[j]);
            const ulonglong2* wq = w1q[i0 + j];
            #pragma unroll
            for (int q = 0; q < 7; q++){
                ulonglong2 w = wq[q];
                fma2(acc[2*q],     xd, w.x);
                fma2(acc[2*q + 1], xd, w.y);
            }
        }
    }
    {   // tail element i = 224
        u64 xd = pack2(xr[224], xr[224]);
        const ulonglong2* wq = w1q[224];
        #pragma unroll
        for (int q = 0; q < 7; q++){
            ulonglong2 w = wq[q];
            fma2(acc[2*q],     xd, w.x);
            fma2(acc[2*q + 1], xd, w.y);
        }
    }

    float accf[NC];
    #pragma unroll
    for (int p = 0; p < 14; p++){
        float2 v = unpack2(acc[p]);
        accf[2*p] = v.x; accf[2*p + 1] = v.y;
    }

    // Epilogue: h = scale*acc + b1 ; a = gelu_exact(h) ;
    // sum_k o[s,k] = (sum_h a*W2sum + b2sum) * 2^s ; r = total/28 ; softplus
    float total = 0.f;
    float scale = 1.f, inv = 1.f;
    #pragma unroll
    for (int s = 0; s < NS; s++){
        float part = sb2s[s];
        #pragma unroll
        for (int h = 0; h < HID; h++){
            int c = s * HID + h;
            float hv = fmaf(accf[c], scale, sb1[c]);
            float av = 0.5f * hv * (1.0f + erff(hv * 0.70710678118654752f));
            part = fmaf(av, sw2s[c], part);
        }
        total = fmaf(part, inv, total);
        scale *= 0.5f;
        inv   *= 2.f;
    }
    float r = total * (1.0f / 28.0f);
    // stable softplus == jax.nn.softplus
    out[row] = fmaxf(r, 0.f) + log1pf(expf(-fabsf(r)));
}

extern "C" void kernel_launch(void* const* d_in, const int* in_sizes, int n_in,
                              void* d_out, int out_size)
{
    const float* x  = (const float*)d_in[0];
    const float* W1 = (const float*)d_in[1];
    const float* b1 = (const float*)d_in[2];
    const float* W2 = (const float*)d_in[3];
    const float* b2 = (const float*)d_in[4];
    float* out = (float*)d_out;

    int B = in_sizes[0] / IN_DIM;
    int blocks = (B + NTHREADS - 1) / NTHREADS;
    fused_msmlp_kernel<<<blocks, NTHREADS>>>(x, W1, b1, W2, b2, out, B);
}

// round 2
// speedup vs baseline: 1.0545x; 1.0545x over previous
#include <cuda_runtime.h>

typedef unsigned long long u64;

// ---- packed f32x2 helpers (sm_100+; ptxas never emits FFMA2 from C++) ----
__device__ __forceinline__ u64 pack2(float a, float b){
    u64 r; asm("mov.b64 %0, {%1, %2};" : "=l"(r) : "f"(a), "f"(b)); return r;
}
__device__ __forceinline__ void fma2(u64 &d, u64 a, u64 b){
    asm("fma.rn.f32x2 %0, %1, %2, %0;" : "+l"(d) : "l"(a), "l"(b));
}
__device__ __forceinline__ float2 unpack2(u64 v){
    float2 r; asm("mov.b64 {%0, %1}, %2;" : "=f"(r.x), "=f"(r.y) : "l"(v)); return r;
}

constexpr int IN_DIM = 225;   // 15*15
constexpr int NS     = 7;     // n_scales
constexpr int HID    = 4;
constexpr int NC     = NS * HID;  // 28 fused channels, c = s*4+h
constexpr int NT     = 128;       // threads per block
constexpr int R      = 4;         // rows per thread (weight-LDS amortization)
constexpr int CH     = 5;         // k-chunk (225 = 45*5, no tail)

__global__ __launch_bounds__(NT) void fused_msmlp_kernel(
    const float* __restrict__ x,
    const float* __restrict__ W1,   // [7,225,4]
    const float* __restrict__ b1,   // [7,4]
    const float* __restrict__ W2,   // [7,4,4]
    const float* __restrict__ b2,   // [7,4]
    float* __restrict__ out,        // [B]
    int B)
{
    // W1 restaged channel-major: w1q[i] = 7 x ulonglong2, each u64 = channel pair.
    __shared__ ulonglong2 w1q[IN_DIM][7];   // 25.2 KB
    __shared__ float sb1[NC];
    __shared__ float sw2s[NC];              // sum_k W2[s,h,k]
    __shared__ float sb2s[NS];              // sum_k b2[s,k]

    float* w1f = (float*)w1q;
    for (int t = threadIdx.x; t < IN_DIM * NC; t += NT){
        int i = t / NC, c = t - i * NC;
        int s = c >> 2, h = c & 3;
        w1f[i * NC + c] = W1[(s * IN_DIM + i) * HID + h];
    }
    if (threadIdx.x < NC){
        int c = threadIdx.x;
        sb1[c] = b1[c];
        float w2s = 0.f;
        #pragma unroll
        for (int k = 0; k < HID; k++) w2s += W2[c * HID + k];
        sw2s[c] = w2s;
    }
    if (threadIdx.x < NS){
        int s = threadIdx.x;
        float bs = 0.f;
        #pragma unroll
        for (int k = 0; k < HID; k++) bs += b2[s * HID + k];
        sb2s[s] = bs;
    }
    __syncthreads();

    long long row0 = ((long long)blockIdx.x * NT + threadIdx.x) * R;
    if (row0 >= B) return;
    const float* xr = x + row0 * IN_DIM;

    // acc[r][p]: packed pair of channels (2p, 2p+1) for row r
    u64 acc[R][14];
    #pragma unroll
    for (int r = 0; r < R; r++)
        #pragma unroll
        for (int p = 0; p < 14; p++) acc[r][p] = 0ull;

    #pragma unroll 1
    for (int i0 = 0; i0 < IN_DIM; i0 += CH){
        // prefetch x chunk for all R rows
        float xv[R][CH];
        #pragma unroll
        for (int r = 0; r < R; r++)
            #pragma unroll
            for (int j = 0; j < CH; j++)
                xv[r][j] = xr[r * IN_DIM + i0 + j];

        #pragma unroll
        for (int j = 0; j < CH; j++){
            // 7 uniform LDS.128 -> 28 channels of W1[i], shared by R rows
            ulonglong2 w[7];
            const ulonglong2* wq = w1q[i0 + j];
            #pragma unroll
            for (int q = 0; q < 7; q++) w[q] = wq[q];

            #pragma unroll
            for (int r = 0; r < R; r++){
                u64 xd = pack2(xv[r][j], xv[r][j]);
                #pragma unroll
                for (int q = 0; q < 7; q++){
                    fma2(acc[r][2*q],     xd, w[q].x);
                    fma2(acc[r][2*q + 1], xd, w[q].y);
                }
            }
        }
    }

    // Epilogue per row: h = scale*acc + b1 ; a = gelu_exact(h)
    // row value r = (sum_s 2^s * (b2sum_s + sum_h a*W2sum)) / 28 ; softplus
    #pragma unroll
    for (int r = 0; r < R; r++){
        float accf[NC];
        #pragma unroll
        for (int p = 0; p < 14; p++){
            float2 v = unpack2(acc[r][p]);
            accf[2*p] = v.x; accf[2*p + 1] = v.y;
        }
        float total = 0.f;
        float scale = 1.f, inv = 1.f;
        #pragma unroll
        for (int s = 0; s < NS; s++){
            float part = sb2s[s];
            #pragma unroll
            for (int h = 0; h < HID; h++){
                int c = s * HID + h;
                float hv = fmaf(accf[c], scale, sb1[c]);
                float av = 0.5f * hv * (1.0f + erff(hv * 0.70710678118654752f));
                part = fmaf(av, sw2s[c], part);
            }
            total = fmaf(part, inv, total);
            scale *= 0.5f;
            inv   *= 2.f;
        }
        float v = total * (1.0f / 28.0f);
        out[row0 + r] = fmaxf(v, 0.f) + log1pf(expf(-fabsf(v)));
    }
}

extern "C" void kernel_launch(void* const* d_in, const int* in_sizes, int n_in,
                              void* d_out, int out_size)
{
    const float* x  = (const float*)d_in[0];
    const float* W1 = (const float*)d_in[1];
    const float* b1 = (const float*)d_in[2];
    const float* W2 = (const float*)d_in[3];
    const float* b2 = (const float*)d_in[4];
    float* out = (float*)d_out;

    int B = in_sizes[0] / IN_DIM;
    long long rowsPerBlock = (long long)NT * R;
    int blocks = (int)((B + rowsPerBlock - 1) / rowsPerBlock);
    fused_msmlp_kernel<<<blocks, NT>>>(x, W1, b1, W2, b2, out, B);
}